// round 11
// baseline (speedup 1.0000x reference)
#include <cuda_runtime.h>

// Globalizer: per-point 2x2 rotation over a [64, 4096, 128] f32 stream.
// x: [B, N, 128] f32 ; R: [B, N, 2, 2] f32 (r00, r01, r10, r11 per point)
// y0 = r00*x0 + r01*x1 ; y1 = r10*x0 + r11*x1 per consecutive pair.
//
// v8 (256-bit) accesses + block-stride unroll-2: thread handles chunks
// t and t+THREADS within its block's 2*THREADS-chunk region. Both loads
// are perfectly coalesced (each warp instruction covers 1024B densely);
// the two loads are independent -> MLP_p1 = 2 without the register blowup
// or queue contention of deeper batching. Grid divides exactly:
// 4,194,304 chunks = 8192 regions of 512 = 4096 blocks x 256 thr x 2.

#define THREADS 256

__global__ __launch_bounds__(THREADS) void rot2_kernel(
    const float* __restrict__ x,
    const float4* __restrict__ R,
    float* __restrict__ out)
{
    int t0 = blockIdx.x * (2 * THREADS) + threadIdx.x;
    int t1 = t0 + THREADS;

    // 128 floats per point = 16 chunks per point
    float4 ra = __ldg(&R[t0 >> 4]);
    float4 rb = __ldg(&R[t1 >> 4]);

    const float* px0 = x   + ((size_t)t0 << 3);
    const float* px1 = x   + ((size_t)t1 << 3);
    float*       po0 = out + ((size_t)t0 << 3);
    float*       po1 = out + ((size_t)t1 << 3);

    float a0, a1, a2, a3, a4, a5, a6, a7;
    float b0, b1, b2, b3, b4, b5, b6, b7;
    asm volatile(
        "ld.global.v8.f32 {%0,%1,%2,%3,%4,%5,%6,%7}, [%8];"
        : "=f"(a0), "=f"(a1), "=f"(a2), "=f"(a3),
          "=f"(a4), "=f"(a5), "=f"(a6), "=f"(a7)
        : "l"(px0));
    asm volatile(
        "ld.global.v8.f32 {%0,%1,%2,%3,%4,%5,%6,%7}, [%8];"
        : "=f"(b0), "=f"(b1), "=f"(b2), "=f"(b3),
          "=f"(b4), "=f"(b5), "=f"(b6), "=f"(b7)
        : "l"(px1));

    float u0 = fmaf(ra.x, a0, ra.y * a1);
    float u1 = fmaf(ra.z, a0, ra.w * a1);
    float u2 = fmaf(ra.x, a2, ra.y * a3);
    float u3 = fmaf(ra.z, a2, ra.w * a3);
    float u4 = fmaf(ra.x, a4, ra.y * a5);
    float u5 = fmaf(ra.z, a4, ra.w * a5);
    float u6 = fmaf(ra.x, a6, ra.y * a7);
    float u7 = fmaf(ra.z, a6, ra.w * a7);

    asm volatile(
        "st.global.v8.f32 [%0], {%1,%2,%3,%4,%5,%6,%7,%8};"
        :: "l"(po0),
           "f"(u0), "f"(u1), "f"(u2), "f"(u3),
           "f"(u4), "f"(u5), "f"(u6), "f"(u7)
        : "memory");

    float v0 = fmaf(rb.x, b0, rb.y * b1);
    float v1 = fmaf(rb.z, b0, rb.w * b1);
    float v2 = fmaf(rb.x, b2, rb.y * b3);
    float v3 = fmaf(rb.z, b2, rb.w * b3);
    float v4 = fmaf(rb.x, b4, rb.y * b5);
    float v5 = fmaf(rb.z, b4, rb.w * b5);
    float v6 = fmaf(rb.x, b6, rb.y * b7);
    float v7 = fmaf(rb.z, b6, rb.w * b7);

    asm volatile(
        "st.global.v8.f32 [%0], {%1,%2,%3,%4,%5,%6,%7,%8};"
        :: "l"(po1),
           "f"(v0), "f"(v1), "f"(v2), "f"(v3),
           "f"(v4), "f"(v5), "f"(v6), "f"(v7)
        : "memory");
}

extern "C" void kernel_launch(void* const* d_in, const int* in_sizes, int n_in,
                              void* d_out, int out_size)
{
    const float*  x = (const float*)d_in[0];
    const float4* R = (const float4*)d_in[1];
    float* out = (float*)d_out;

    int n8 = out_size / 8;                  // 4,194,304 chunks of 8 floats
    int blocks = n8 / (2 * THREADS);        // 8192, exact
    rot2_kernel<<<blocks, THREADS>>>(x, R, out);
}